// round 1
// baseline (speedup 1.0000x reference)
#include <cuda_runtime.h>

// ---------------------------------------------------------------------------
// Q_NetWork: time-LSTM (in=10, hid=32) over T=16384 steps, feeding three
// masked LSTMs (in=32, hid=40), fused MLP -> scalar.
//
// Plan:
//   K1 (parallel): Gx_time[t] = time_Wih @ x_t + (bih+bhh) for all t.
//   K2 (persistent, 4 blocks): block0 = time-LSTM recurrence producing ys[t],
//       publishing progress with release semantics; blocks 1..3 = masked
//       LSTMs (types 1,0,2) consuming ys[t] at their masked steps only,
//       computing Wih@ys inline.
//   K3: fusion + 2-layer MLP -> d_out[0].
// ---------------------------------------------------------------------------

#define TSTEPS 16384
#define NITEMS 1000

typedef unsigned long long ull;

// global scratch (device globals: allocation-free per harness rules)
__device__ float g_gx[TSTEPS * 128];   // 8 MB: time-LSTM input gate preacts
__device__ float g_ys[TSTEPS * 32];    // 2 MB: time-LSTM hidden states
__device__ float g_H[3][40];           // final hidden per mask type
__device__ int   g_progress;           // producer progress (steps completed)

// ---- fast math helpers ----------------------------------------------------
__device__ __forceinline__ float fsig(float x) {
    return __fdividef(1.0f, 1.0f + __expf(-x));
}
__device__ __forceinline__ float ftanh_(float x) {
    // tanh via exp: ~1e-6 rel error (tanh.approx would be too coarse over 16k steps)
    return 1.0f - __fdividef(2.0f, __expf(2.0f * x) + 1.0f);
}

// ---- packed f32x2 FMA (sm_103a FFMA2) -------------------------------------
__device__ __forceinline__ ull pack2(float lo, float hi) {
    ull r; asm("mov.b64 %0, {%1,%2};" : "=l"(r) : "f"(lo), "f"(hi)); return r;
}
__device__ __forceinline__ void unpack2(ull v, float& lo, float& hi) {
    asm("mov.b64 {%0,%1}, %2;" : "=f"(lo), "=f"(hi) : "l"(v));
}
__device__ __forceinline__ void ffma2(ull& acc, ull a, ull b) {
    asm("fma.rn.f32x2 %0, %1, %2, %0;" : "+l"(acc) : "l"(a), "l"(b));
}

// ---------------------------------------------------------------------------
// K1: per-t gate preactivations for the time LSTM (fully parallel).
// x_t = [dwell[t], proj[type[t]] @ item_emb[:, items[t]] (9)]
// Gx[t][r] = (bih+bhh)[r] + sum_i Wih[r][i] * x_t[i]
// ---------------------------------------------------------------------------
__global__ void k_precompute_gx(const int* __restrict__ items,
                                const int* __restrict__ types,
                                const float* __restrict__ dwell,
                                const float* __restrict__ item_emb,
                                const float* __restrict__ click,
                                const float* __restrict__ purchase,
                                const float* __restrict__ skip,
                                const float* __restrict__ Wih,
                                const float* __restrict__ bih,
                                const float* __restrict__ bhh)
{
    int t = blockIdx.x;
    int tid = threadIdx.x;   // 128 threads

    if (t == 0 && tid == 0) g_progress = 0;  // reset before pipeline kernel

    __shared__ float ie[32];
    __shared__ float xs[10];

    if (tid < 32) ie[tid] = item_emb[tid * NITEMS + items[t]];
    __syncthreads();

    if (tid < 9) {
        int ty = types[t];
        const float* P = (ty == 0) ? click : (ty == 1) ? purchase : skip;
        P += tid * 32;
        float s = 0.0f;
#pragma unroll
        for (int j = 0; j < 32; j++) s += P[j] * ie[j];
        xs[1 + tid] = s;
    } else if (tid == 9) {
        xs[0] = dwell[t];
    }
    __syncthreads();

    float acc = bih[tid] + bhh[tid];
    const float* w = Wih + tid * 10;
#pragma unroll
    for (int i = 0; i < 10; i++) acc += w[i] * xs[i];
    g_gx[t * 128 + tid] = acc;
}

// ---------------------------------------------------------------------------
// K2: persistent pipeline. grid = 4 blocks x 160 threads.
//   block 0: producer (time LSTM), 128 active threads (one gate row each)
//   blocks 1..3: consumers for mask types 1 (p), 0 (c), 2 (s)
// ---------------------------------------------------------------------------
__global__ void __launch_bounds__(160, 1)
k_pipeline(const int* __restrict__ types,
           const float* __restrict__ time_Whh,
           const float* __restrict__ p_Wih, const float* __restrict__ p_Whh,
           const float* __restrict__ p_bih, const float* __restrict__ p_bhh,
           const float* __restrict__ c_Wih, const float* __restrict__ c_Whh,
           const float* __restrict__ c_bih, const float* __restrict__ c_bhh,
           const float* __restrict__ s_Wih, const float* __restrict__ s_Whh,
           const float* __restrict__ s_bih, const float* __restrict__ s_bhh)
{
    int tid = threadIdx.x;

    if (blockIdx.x == 0) {
        // ---------------- producer: time LSTM ----------------
        __shared__ __align__(16) float h_sh[32];
        __shared__ float gsh[128];

        ull w2[16];
        if (tid < 128) {
            const ull* wp = reinterpret_cast<const ull*>(time_Whh) + tid * 16;
#pragma unroll
            for (int i = 0; i < 16; i++) w2[i] = wp[i];
        }
        float c = 0.0f;
        if (tid < 32) h_sh[tid] = 0.0f;
        float gx = (tid < 128) ? g_gx[tid] : 0.0f;
        __syncthreads();

        for (int t = 0; t < TSTEPS; t++) {
            // prefetch next step's preact (hides L2 latency)
            float gxn = (tid < 128 && t + 1 < TSTEPS) ? g_gx[(t + 1) * 128 + tid] : 0.0f;

            if (tid < 128) {
                ull a0 = pack2(gx, 0.0f);
                ull a1 = pack2(0.0f, 0.0f);
                const ulonglong2* hp = reinterpret_cast<const ulonglong2*>(h_sh);
#pragma unroll
                for (int q = 0; q < 8; q++) {
                    ulonglong2 hv = hp[q];            // LDS.128 broadcast
                    ffma2(a0, w2[2 * q], hv.x);
                    ffma2(a1, w2[2 * q + 1], hv.y);
                }
                float l0, u0, l1, u1;
                unpack2(a0, l0, u0); unpack2(a1, l1, u1);
                float g = (l0 + l1) + (u0 + u1);
                float v = ((tid >> 5) == 2) ? ftanh_(g) : fsig(g);  // rows 64..95 = g-gate
                gsh[tid] = v;
            }
            __syncthreads();

            if (tid < 32) {
                float ig = gsh[tid], fg = gsh[32 + tid];
                float gg = gsh[64 + tid], og = gsh[96 + tid];
                c = fg * c + ig * gg;
                float h = og * ftanh_(c);
                h_sh[tid] = h;
                g_ys[t * 32 + tid] = h;
            }
            __syncthreads();

            if (tid == 0) {
                __threadfence();                       // release ys[t]
                *((volatile int*)&g_progress) = t + 1;
            }
            gx = gxn;
        }
    } else {
        // ---------------- consumer: masked LSTM ----------------
        __shared__ unsigned char tysh[TSTEPS];   // 16 KB
        __shared__ __align__(16) float h_sh[40];
        __shared__ __align__(16) float x_sh[32];
        __shared__ float gsh[160];

        int b = blockIdx.x;
        int myType = (b == 1) ? 1 : (b == 2) ? 0 : 2;
        const float* Wih = (b == 1) ? p_Wih : (b == 2) ? c_Wih : s_Wih;
        const float* Whh = (b == 1) ? p_Whh : (b == 2) ? c_Whh : s_Whh;
        const float* bih = (b == 1) ? p_bih : (b == 2) ? c_bih : s_bih;
        const float* bhh = (b == 1) ? p_bhh : (b == 2) ? c_bhh : s_bhh;

        for (int i = tid; i < TSTEPS; i += 160)
            tysh[i] = (unsigned char)types[i];

        ull wih2[16], whh2[20];
        {
            const ull* p = reinterpret_cast<const ull*>(Wih) + tid * 16;
#pragma unroll
            for (int i = 0; i < 16; i++) wih2[i] = p[i];
            const ull* q = reinterpret_cast<const ull*>(Whh) + tid * 20;
#pragma unroll
            for (int i = 0; i < 20; i++) whh2[i] = q[i];
        }
        float bsum = bih[tid] + bhh[tid];
        float c = 0.0f;
        if (tid < 40) h_sh[tid] = 0.0f;
        __syncthreads();

        int seen = 0;
        for (int t = 0; t < TSTEPS; t++) {
            if (tysh[t] != (unsigned char)myType) continue;   // uniform across block

            if (tid == 0 && seen <= t) {
                while ((seen = *((volatile int*)&g_progress)) <= t) { }
                __threadfence();                    // acquire
            }
            __syncthreads();

            if (tid < 32) x_sh[tid] = __ldcg(&g_ys[t * 32 + tid]);
            __syncthreads();

            ull a0 = pack2(bsum, 0.0f);
            ull a1 = pack2(0.0f, 0.0f);
            const ulonglong2* xp = reinterpret_cast<const ulonglong2*>(x_sh);
#pragma unroll
            for (int q = 0; q < 8; q++) {
                ulonglong2 v = xp[q];
                ffma2(a0, wih2[2 * q], v.x);
                ffma2(a1, wih2[2 * q + 1], v.y);
            }
            const ulonglong2* hp = reinterpret_cast<const ulonglong2*>(h_sh);
#pragma unroll
            for (int q = 0; q < 10; q++) {
                ulonglong2 v = hp[q];
                ffma2(a0, whh2[2 * q], v.x);
                ffma2(a1, whh2[2 * q + 1], v.y);
            }
            float l0, u0, l1, u1;
            unpack2(a0, l0, u0); unpack2(a1, l1, u1);
            float g = (l0 + l1) + (u0 + u1);
            float v = (tid / 40 == 2) ? ftanh_(g) : fsig(g);   // rows 80..119 = g-gate
            gsh[tid] = v;
            __syncthreads();

            if (tid < 40) {
                float ig = gsh[tid], fg = gsh[40 + tid];
                float gg = gsh[80 + tid], og = gsh[120 + tid];
                c = fg * c + ig * gg;
                h_sh[tid] = og * ftanh_(c);
            }
            __syncthreads();
        }

        if (tid < 40) g_H[myType][tid] = h_sh[tid];
    }
}

// ---------------------------------------------------------------------------
// K3: fusion + MLP -> scalar
// fusion = [next_e(32), user_e(32), H_r(32), H_s(40), H_c(40), H_p(40)]
// ---------------------------------------------------------------------------
__global__ void k_mlp(const int* __restrict__ user,
                      const int* __restrict__ nextitem,
                      const float* __restrict__ item_emb,
                      const float* __restrict__ user_emb,
                      const float* __restrict__ out1_W,
                      const float* __restrict__ out1_b,
                      const float* __restrict__ out2_W,
                      const float* __restrict__ out2_b,
                      float* __restrict__ out)
{
    __shared__ float f[216];
    __shared__ float r16[16];
    int tid = threadIdx.x;   // 64 threads
    int u = user[0], ni = nextitem[0];

    if (tid < 32) {
        f[tid]      = item_emb[tid * NITEMS + ni];
        f[32 + tid] = user_emb[tid * NITEMS + u];
        f[64 + tid] = g_ys[(TSTEPS - 1) * 32 + tid];   // H_r
    }
    if (tid < 40) {
        f[96 + tid]  = g_H[2][tid];   // H_s (type 2)
        f[136 + tid] = g_H[0][tid];   // H_c (type 0)
        f[176 + tid] = g_H[1][tid];   // H_p (type 1)
    }
    __syncthreads();

    if (tid < 16) {
        float acc = out1_b[tid];
        const float* w = out1_W + tid * 216;
        for (int k = 0; k < 216; k++) acc += w[k] * f[k];
        r16[tid] = fmaxf(acc, 0.0f);
    }
    __syncthreads();

    if (tid == 0) {
        float acc = out2_b[0];
        for (int k = 0; k < 16; k++) acc += out2_W[k] * r16[k];
        out[0] = acc;
    }
}

// ---------------------------------------------------------------------------
extern "C" void kernel_launch(void* const* d_in, const int* in_sizes, int n_in,
                              void* d_out, int out_size)
{
    const int*   user      = (const int*)  d_in[0];
    const int*   nextitem  = (const int*)  d_in[1];
    const int*   seq_items = (const int*)  d_in[2];
    const int*   seq_types = (const int*)  d_in[3];
    const float* dwell     = (const float*)d_in[4];
    const float* item_emb  = (const float*)d_in[5];
    const float* user_emb  = (const float*)d_in[6];
    const float* click     = (const float*)d_in[7];
    const float* purchase  = (const float*)d_in[8];
    const float* skipp     = (const float*)d_in[9];
    const float* time_Wih  = (const float*)d_in[10];
    const float* time_Whh  = (const float*)d_in[11];
    const float* time_bih  = (const float*)d_in[12];
    const float* time_bhh  = (const float*)d_in[13];
    const float* p_Wih     = (const float*)d_in[14];
    const float* p_Whh     = (const float*)d_in[15];
    const float* p_bih     = (const float*)d_in[16];
    const float* p_bhh     = (const float*)d_in[17];
    const float* c_Wih     = (const float*)d_in[18];
    const float* c_Whh     = (const float*)d_in[19];
    const float* c_bih     = (const float*)d_in[20];
    const float* c_bhh     = (const float*)d_in[21];
    const float* s_Wih     = (const float*)d_in[22];
    const float* s_Whh     = (const float*)d_in[23];
    const float* s_bih     = (const float*)d_in[24];
    const float* s_bhh     = (const float*)d_in[25];
    const float* out1_W    = (const float*)d_in[26];
    const float* out1_b    = (const float*)d_in[27];
    const float* out2_W    = (const float*)d_in[28];
    const float* out2_b    = (const float*)d_in[29];

    k_precompute_gx<<<TSTEPS, 128>>>(seq_items, seq_types, dwell, item_emb,
                                     click, purchase, skipp,
                                     time_Wih, time_bih, time_bhh);

    k_pipeline<<<4, 160>>>(seq_types, time_Whh,
                           p_Wih, p_Whh, p_bih, p_bhh,
                           c_Wih, c_Whh, c_bih, c_bhh,
                           s_Wih, s_Whh, s_bih, s_bhh);

    k_mlp<<<1, 64>>>(user, nextitem, item_emb, user_emb,
                     out1_W, out1_b, out2_W, out2_b, (float*)d_out);
}

// round 2
// speedup vs baseline: 2.1497x; 2.1497x over previous
#include <cuda_runtime.h>

// ---------------------------------------------------------------------------
// Q_NetWork: time-LSTM (in=10, hid=32) over T=16384 steps, feeding three
// masked LSTMs (in=32, hid=40), fused MLP -> scalar.
//
// R2 changes vs R1 (11.06 ms):
//   * progress published every 32 steps via st.release.gpu (was: per-step
//     __threadfence + volatile store -> ~600+ cyc/step of ordering overhead)
//   * all nonlinearities via HW MUFU tanh.approx (lat 16) instead of
//     EX2+RCP chains (~40 cyc each)
// ---------------------------------------------------------------------------

#define TSTEPS 16384
#define NITEMS 1000
#define PUB_CHUNK 32

typedef unsigned long long ull;

// global scratch (device globals: allocation-free per harness rules)
__device__ float g_gx[TSTEPS * 128];   // 8 MB: time-LSTM input gate preacts
__device__ float g_ys[TSTEPS * 32];    // 2 MB: time-LSTM hidden states
__device__ float g_H[3][40];           // final hidden per mask type
__device__ int   g_progress;           // producer progress (steps completed)

// ---- fast math helpers ----------------------------------------------------
__device__ __forceinline__ float ftanh_(float x) {
    float y; asm("tanh.approx.f32 %0, %1;" : "=f"(y) : "f"(x)); return y;
}
__device__ __forceinline__ float fsig(float x) {
    return fmaf(0.5f, ftanh_(0.5f * x), 0.5f);
}

// ---- scoped release/acquire for the progress flag -------------------------
__device__ __forceinline__ void st_release_gpu(int* p, int v) {
    asm volatile("st.release.gpu.global.b32 [%0], %1;" :: "l"(p), "r"(v) : "memory");
}
__device__ __forceinline__ int ld_acquire_gpu(const int* p) {
    int v; asm volatile("ld.acquire.gpu.global.b32 %0, [%1];" : "=r"(v) : "l"(p) : "memory");
    return v;
}

// ---- packed f32x2 FMA (sm_103a FFMA2) -------------------------------------
__device__ __forceinline__ ull pack2(float lo, float hi) {
    ull r; asm("mov.b64 %0, {%1,%2};" : "=l"(r) : "f"(lo), "f"(hi)); return r;
}
__device__ __forceinline__ void unpack2(ull v, float& lo, float& hi) {
    asm("mov.b64 {%0,%1}, %2;" : "=f"(lo), "=f"(hi) : "l"(v));
}
__device__ __forceinline__ void ffma2(ull& acc, ull a, ull b) {
    asm("fma.rn.f32x2 %0, %1, %2, %0;" : "+l"(acc) : "l"(a), "l"(b));
}

// ---------------------------------------------------------------------------
// K1: per-t gate preactivations for the time LSTM (fully parallel).
// ---------------------------------------------------------------------------
__global__ void k_precompute_gx(const int* __restrict__ items,
                                const int* __restrict__ types,
                                const float* __restrict__ dwell,
                                const float* __restrict__ item_emb,
                                const float* __restrict__ click,
                                const float* __restrict__ purchase,
                                const float* __restrict__ skip,
                                const float* __restrict__ Wih,
                                const float* __restrict__ bih,
                                const float* __restrict__ bhh)
{
    int t = blockIdx.x;
    int tid = threadIdx.x;   // 128 threads

    if (t == 0 && tid == 0) g_progress = 0;  // reset before pipeline kernel

    __shared__ float ie[32];
    __shared__ float xs[10];

    if (tid < 32) ie[tid] = item_emb[tid * NITEMS + items[t]];
    __syncthreads();

    if (tid < 9) {
        int ty = types[t];
        const float* P = (ty == 0) ? click : (ty == 1) ? purchase : skip;
        P += tid * 32;
        float s = 0.0f;
#pragma unroll
        for (int j = 0; j < 32; j++) s += P[j] * ie[j];
        xs[1 + tid] = s;
    } else if (tid == 9) {
        xs[0] = dwell[t];
    }
    __syncthreads();

    float acc = bih[tid] + bhh[tid];
    const float* w = Wih + tid * 10;
#pragma unroll
    for (int i = 0; i < 10; i++) acc += w[i] * xs[i];
    g_gx[t * 128 + tid] = acc;
}

// ---------------------------------------------------------------------------
// K2: persistent pipeline. grid = 4 blocks x 160 threads.
//   block 0: producer (time LSTM), 128 active threads (one gate row each)
//   blocks 1..3: consumers for mask types 1 (p), 0 (c), 2 (s)
// ---------------------------------------------------------------------------
__global__ void __launch_bounds__(160, 1)
k_pipeline(const int* __restrict__ types,
           const float* __restrict__ time_Whh,
           const float* __restrict__ p_Wih, const float* __restrict__ p_Whh,
           const float* __restrict__ p_bih, const float* __restrict__ p_bhh,
           const float* __restrict__ c_Wih, const float* __restrict__ c_Whh,
           const float* __restrict__ c_bih, const float* __restrict__ c_bhh,
           const float* __restrict__ s_Wih, const float* __restrict__ s_Whh,
           const float* __restrict__ s_bih, const float* __restrict__ s_bhh)
{
    int tid = threadIdx.x;

    if (blockIdx.x == 0) {
        // ---------------- producer: time LSTM ----------------
        __shared__ __align__(16) float h_sh[32];
        __shared__ float gsh[128];

        ull w2[16];
        if (tid < 128) {
            const ull* wp = reinterpret_cast<const ull*>(time_Whh) + tid * 16;
#pragma unroll
            for (int i = 0; i < 16; i++) w2[i] = wp[i];
        }
        float c = 0.0f;
        if (tid < 32) h_sh[tid] = 0.0f;
        float gx = (tid < 128) ? g_gx[tid] : 0.0f;
        __syncthreads();

        for (int t = 0; t < TSTEPS; t++) {
            // prefetch next step's preact (hides L2 latency)
            float gxn = (tid < 128 && t + 1 < TSTEPS) ? g_gx[(t + 1) * 128 + tid] : 0.0f;

            if (tid < 128) {
                ull a0 = pack2(gx, 0.0f);
                ull a1 = pack2(0.0f, 0.0f);
                const ulonglong2* hp = reinterpret_cast<const ulonglong2*>(h_sh);
#pragma unroll
                for (int q = 0; q < 8; q++) {
                    ulonglong2 hv = hp[q];            // LDS.128 broadcast
                    ffma2(a0, w2[2 * q], hv.x);
                    ffma2(a1, w2[2 * q + 1], hv.y);
                }
                float l0, u0, l1, u1;
                unpack2(a0, l0, u0); unpack2(a1, l1, u1);
                float g = (l0 + l1) + (u0 + u1);
                float v = ((tid >> 5) == 2) ? ftanh_(g) : fsig(g);  // rows 64..95 = g-gate
                gsh[tid] = v;
            }
            __syncthreads();

            if (tid < 32) {
                float ig = gsh[tid], fg = gsh[32 + tid];
                float gg = gsh[64 + tid], og = gsh[96 + tid];
                c = fg * c + ig * gg;
                float h = og * ftanh_(c);
                h_sh[tid] = h;
                g_ys[t * 32 + tid] = h;
            }
            __syncthreads();

            // Publish progress every PUB_CHUNK steps (release store; the bar
            // above gives CTA-scope HB from the g_ys writers to tid 0, which
            // chains transitively through the gpu-scope release/acquire).
            if (tid == 0 && (((t + 1) & (PUB_CHUNK - 1)) == 0)) {
                st_release_gpu(&g_progress, t + 1);
            }
            gx = gxn;
        }
    } else {
        // ---------------- consumer: masked LSTM ----------------
        __shared__ unsigned char tysh[TSTEPS];   // 16 KB
        __shared__ __align__(16) float h_sh[40];
        __shared__ __align__(16) float x_sh[32];
        __shared__ float gsh[160];

        int b = blockIdx.x;
        int myType = (b == 1) ? 1 : (b == 2) ? 0 : 2;
        const float* Wih = (b == 1) ? p_Wih : (b == 2) ? c_Wih : s_Wih;
        const float* Whh = (b == 1) ? p_Whh : (b == 2) ? c_Whh : s_Whh;
        const float* bih = (b == 1) ? p_bih : (b == 2) ? c_bih : s_bih;
        const float* bhh = (b == 1) ? p_bhh : (b == 2) ? c_bhh : s_bhh;

        for (int i = tid; i < TSTEPS; i += 160)
            tysh[i] = (unsigned char)types[i];

        ull wih2[16], whh2[20];
        {
            const ull* p = reinterpret_cast<const ull*>(Wih) + tid * 16;
#pragma unroll
            for (int i = 0; i < 16; i++) wih2[i] = p[i];
            const ull* q = reinterpret_cast<const ull*>(Whh) + tid * 20;
#pragma unroll
            for (int i = 0; i < 20; i++) whh2[i] = q[i];
        }
        float bsum = bih[tid] + bhh[tid];
        float c = 0.0f;
        if (tid < 40) h_sh[tid] = 0.0f;
        __syncthreads();

        int seen = 0;
        for (int t = 0; t < TSTEPS; t++) {
            if (tysh[t] != (unsigned char)myType) continue;   // uniform across block

            if (tid == 0 && seen <= t) {
                while ((seen = ld_acquire_gpu(&g_progress)) <= t) { }
            }
            __syncthreads();

            if (tid < 32) x_sh[tid] = __ldcg(&g_ys[t * 32 + tid]);
            __syncthreads();

            ull a0 = pack2(bsum, 0.0f);
            ull a1 = pack2(0.0f, 0.0f);
            const ulonglong2* xp = reinterpret_cast<const ulonglong2*>(x_sh);
#pragma unroll
            for (int q = 0; q < 8; q++) {
                ulonglong2 v = xp[q];
                ffma2(a0, wih2[2 * q], v.x);
                ffma2(a1, wih2[2 * q + 1], v.y);
            }
            const ulonglong2* hp = reinterpret_cast<const ulonglong2*>(h_sh);
#pragma unroll
            for (int q = 0; q < 10; q++) {
                ulonglong2 v = hp[q];
                ffma2(a0, whh2[2 * q], v.x);
                ffma2(a1, whh2[2 * q + 1], v.y);
            }
            float l0, u0, l1, u1;
            unpack2(a0, l0, u0); unpack2(a1, l1, u1);
            float g = (l0 + l1) + (u0 + u1);
            float v = (tid / 40 == 2) ? ftanh_(g) : fsig(g);   // rows 80..119 = g-gate
            gsh[tid] = v;
            __syncthreads();

            if (tid < 40) {
                float ig = gsh[tid], fg = gsh[40 + tid];
                float gg = gsh[80 + tid], og = gsh[120 + tid];
                c = fg * c + ig * gg;
                h_sh[tid] = og * ftanh_(c);
            }
            __syncthreads();
        }

        if (tid < 40) g_H[myType][tid] = h_sh[tid];
    }
}

// ---------------------------------------------------------------------------
// K3: fusion + MLP -> scalar
// fusion = [next_e(32), user_e(32), H_r(32), H_s(40), H_c(40), H_p(40)]
// ---------------------------------------------------------------------------
__global__ void k_mlp(const int* __restrict__ user,
                      const int* __restrict__ nextitem,
                      const float* __restrict__ item_emb,
                      const float* __restrict__ user_emb,
                      const float* __restrict__ out1_W,
                      const float* __restrict__ out1_b,
                      const float* __restrict__ out2_W,
                      const float* __restrict__ out2_b,
                      float* __restrict__ out)
{
    __shared__ float f[216];
    __shared__ float r16[16];
    int tid = threadIdx.x;   // 64 threads
    int u = user[0], ni = nextitem[0];

    if (tid < 32) {
        f[tid]      = item_emb[tid * NITEMS + ni];
        f[32 + tid] = user_emb[tid * NITEMS + u];
        f[64 + tid] = g_ys[(TSTEPS - 1) * 32 + tid];   // H_r
    }
    if (tid < 40) {
        f[96 + tid]  = g_H[2][tid];   // H_s (type 2)
        f[136 + tid] = g_H[0][tid];   // H_c (type 0)
        f[176 + tid] = g_H[1][tid];   // H_p (type 1)
    }
    __syncthreads();

    if (tid < 16) {
        float acc = out1_b[tid];
        const float* w = out1_W + tid * 216;
        for (int k = 0; k < 216; k++) acc += w[k] * f[k];
        r16[tid] = fmaxf(acc, 0.0f);
    }
    __syncthreads();

    if (tid == 0) {
        float acc = out2_b[0];
        for (int k = 0; k < 16; k++) acc += out2_W[k] * r16[k];
        out[0] = acc;
    }
}

// ---------------------------------------------------------------------------
extern "C" void kernel_launch(void* const* d_in, const int* in_sizes, int n_in,
                              void* d_out, int out_size)
{
    const int*   user      = (const int*)  d_in[0];
    const int*   nextitem  = (const int*)  d_in[1];
    const int*   seq_items = (const int*)  d_in[2];
    const int*   seq_types = (const int*)  d_in[3];
    const float* dwell     = (const float*)d_in[4];
    const float* item_emb  = (const float*)d_in[5];
    const float* user_emb  = (const float*)d_in[6];
    const float* click     = (const float*)d_in[7];
    const float* purchase  = (const float*)d_in[8];
    const float* skipp     = (const float*)d_in[9];
    const float* time_Wih  = (const float*)d_in[10];
    const float* time_Whh  = (const float*)d_in[11];
    const float* time_bih  = (const float*)d_in[12];
    const float* time_bhh  = (const float*)d_in[13];
    const float* p_Wih     = (const float*)d_in[14];
    const float* p_Whh     = (const float*)d_in[15];
    const float* p_bih     = (const float*)d_in[16];
    const float* p_bhh     = (const float*)d_in[17];
    const float* c_Wih     = (const float*)d_in[18];
    const float* c_Whh     = (const float*)d_in[19];
    const float* c_bih     = (const float*)d_in[20];
    const float* c_bhh     = (const float*)d_in[21];
    const float* s_Wih     = (const float*)d_in[22];
    const float* s_Whh     = (const float*)d_in[23];
    const float* s_bih     = (const float*)d_in[24];
    const float* s_bhh     = (const float*)d_in[25];
    const float* out1_W    = (const float*)d_in[26];
    const float* out1_b    = (const float*)d_in[27];
    const float* out2_W    = (const float*)d_in[28];
    const float* out2_b    = (const float*)d_in[29];

    k_precompute_gx<<<TSTEPS, 128>>>(seq_items, seq_types, dwell, item_emb,
                                     click, purchase, skipp,
                                     time_Wih, time_bih, time_bhh);

    k_pipeline<<<4, 160>>>(seq_types, time_Whh,
                           p_Wih, p_Whh, p_bih, p_bhh,
                           c_Wih, c_Whh, c_bih, c_bhh,
                           s_Wih, s_Whh, s_bih, s_bhh);

    k_mlp<<<1, 64>>>(user, nextitem, item_emb, user_emb,
                     out1_W, out1_b, out2_W, out2_b, (float*)d_out);
}

// round 3
// speedup vs baseline: 2.2651x; 1.0537x over previous
#include <cuda_runtime.h>

// ---------------------------------------------------------------------------
// Q_NetWork: time-LSTM (in=10, hid=32) over T=16384 steps, feeding three
// masked LSTMs (in=32, hid=40), fused MLP -> scalar.
//
// R3 changes vs R2 (5.14 ms):
//   * producer rewritten as a SINGLE WARP, lane l owns element l and all 4 of
//     its gate rows (i,f,g,o) -> cell update is lane-local, zero __syncthreads
//     on the 16384-step critical path (one __syncwarp per step for the
//     STS(h) -> LDS.128(h) broadcast).
//   * g_gx stored [t][elem][gate] so each lane prefetches its 4 preacts with
//     one LDG.128.
// ---------------------------------------------------------------------------

#define TSTEPS 16384
#define NITEMS 1000
#define PUB_CHUNK 32

typedef unsigned long long ull;

// global scratch (device globals: allocation-free per harness rules)
__device__ float g_gx[TSTEPS * 128];   // 8 MB: [t][elem(32)][gate(4)] preacts
__device__ float g_ys[TSTEPS * 32];    // 2 MB: time-LSTM hidden states
__device__ float g_H[3][40];           // final hidden per mask type
__device__ int   g_progress;           // producer progress (steps completed)

// ---- fast math helpers ----------------------------------------------------
__device__ __forceinline__ float ftanh_(float x) {
    float y; asm("tanh.approx.f32 %0, %1;" : "=f"(y) : "f"(x)); return y;
}
__device__ __forceinline__ float fsig(float x) {
    return fmaf(0.5f, ftanh_(0.5f * x), 0.5f);
}

// ---- scoped sync primitives ----------------------------------------------
__device__ __forceinline__ void fence_gpu() {
    asm volatile("fence.acq_rel.gpu;" ::: "memory");
}
__device__ __forceinline__ void st_relaxed_gpu(int* p, int v) {
    asm volatile("st.relaxed.gpu.global.b32 [%0], %1;" :: "l"(p), "r"(v) : "memory");
}
__device__ __forceinline__ int ld_acquire_gpu(const int* p) {
    int v; asm volatile("ld.acquire.gpu.global.b32 %0, [%1];" : "=r"(v) : "l"(p) : "memory");
    return v;
}

// ---- packed f32x2 FMA (sm_103a FFMA2) -------------------------------------
__device__ __forceinline__ ull pack2(float lo, float hi) {
    ull r; asm("mov.b64 %0, {%1,%2};" : "=l"(r) : "f"(lo), "f"(hi)); return r;
}
__device__ __forceinline__ void unpack2(ull v, float& lo, float& hi) {
    asm("mov.b64 {%0,%1}, %2;" : "=f"(lo), "=f"(hi) : "l"(v));
}
__device__ __forceinline__ void ffma2(ull& acc, ull a, ull b) {
    asm("fma.rn.f32x2 %0, %1, %2, %0;" : "+l"(acc) : "l"(a), "l"(b));
}
__device__ __forceinline__ float red2(ull v) {
    float lo, hi; unpack2(v, lo, hi); return lo + hi;
}

// ---------------------------------------------------------------------------
// K1: per-t gate preactivations for the time LSTM (fully parallel).
// Row r = gate*32 + elem; stored at g_gx[t*128 + elem*4 + gate].
// ---------------------------------------------------------------------------
__global__ void k_precompute_gx(const int* __restrict__ items,
                                const int* __restrict__ types,
                                const float* __restrict__ dwell,
                                const float* __restrict__ item_emb,
                                const float* __restrict__ click,
                                const float* __restrict__ purchase,
                                const float* __restrict__ skip,
                                const float* __restrict__ Wih,
                                const float* __restrict__ bih,
                                const float* __restrict__ bhh)
{
    int t = blockIdx.x;
    int tid = threadIdx.x;   // 128 threads

    if (t == 0 && tid == 0) g_progress = 0;  // reset before pipeline kernel

    __shared__ float ie[32];
    __shared__ float xs[10];

    if (tid < 32) ie[tid] = item_emb[tid * NITEMS + items[t]];
    __syncthreads();

    if (tid < 9) {
        int ty = types[t];
        const float* P = (ty == 0) ? click : (ty == 1) ? purchase : skip;
        P += tid * 32;
        float s = 0.0f;
#pragma unroll
        for (int j = 0; j < 32; j++) s += P[j] * ie[j];
        xs[1 + tid] = s;
    } else if (tid == 9) {
        xs[0] = dwell[t];
    }
    __syncthreads();

    float acc = bih[tid] + bhh[tid];
    const float* w = Wih + tid * 10;
#pragma unroll
    for (int i = 0; i < 10; i++) acc += w[i] * xs[i];
    int gate = tid >> 5, elem = tid & 31;
    g_gx[t * 128 + elem * 4 + gate] = acc;
}

// ---------------------------------------------------------------------------
// K2: persistent pipeline. grid = 4 blocks x 160 threads.
//   block 0: producer (time LSTM), warp 0 only (32 lanes, lane = h element)
//   blocks 1..3: consumers for mask types 1 (p), 0 (c), 2 (s)
// ---------------------------------------------------------------------------
__global__ void __launch_bounds__(160, 1)
k_pipeline(const int* __restrict__ types,
           const float* __restrict__ time_Whh,
           const float* __restrict__ p_Wih, const float* __restrict__ p_Whh,
           const float* __restrict__ p_bih, const float* __restrict__ p_bhh,
           const float* __restrict__ c_Wih, const float* __restrict__ c_Whh,
           const float* __restrict__ c_bih, const float* __restrict__ c_bhh,
           const float* __restrict__ s_Wih, const float* __restrict__ s_Whh,
           const float* __restrict__ s_bih, const float* __restrict__ s_bhh)
{
    int tid = threadIdx.x;

    if (blockIdx.x == 0) {
        // ---------------- producer: time LSTM, single warp ----------------
        if (tid >= 32) return;            // warps 1..4 idle; no __syncthreads here
        int l = tid;

        __shared__ __align__(16) float h_sh[32];

        // lane l holds Whh rows l (i), 32+l (f), 64+l (g), 96+l (o): 16 ull each
        ull wi[16], wf[16], wg[16], wo[16];
        {
            const ull* pi = reinterpret_cast<const ull*>(time_Whh + (     l) * 32);
            const ull* pf = reinterpret_cast<const ull*>(time_Whh + (32 + l) * 32);
            const ull* pg = reinterpret_cast<const ull*>(time_Whh + (64 + l) * 32);
            const ull* po = reinterpret_cast<const ull*>(time_Whh + (96 + l) * 32);
#pragma unroll
            for (int i = 0; i < 16; i++) { wi[i] = pi[i]; wf[i] = pf[i]; wg[i] = pg[i]; wo[i] = po[i]; }
        }

        float c = 0.0f;
        h_sh[l] = 0.0f;
        float4 gx = *reinterpret_cast<const float4*>(&g_gx[l * 4]);
        __syncwarp();

        for (int t = 0; t < TSTEPS; t++) {
            // prefetch next step's preacts (one LDG.128; hidden behind step)
            float4 gxn;
            if (t + 1 < TSTEPS)
                gxn = *reinterpret_cast<const float4*>(&g_gx[(t + 1) * 128 + l * 4]);
            else
                gxn = make_float4(0.f, 0.f, 0.f, 0.f);

            ull ai = pack2(gx.x, 0.0f);
            ull af = pack2(gx.y, 0.0f);
            ull ag = pack2(gx.z, 0.0f);
            ull ao = pack2(gx.w, 0.0f);
            const ulonglong2* hp = reinterpret_cast<const ulonglong2*>(h_sh);
#pragma unroll
            for (int q = 0; q < 8; q++) {
                ulonglong2 hv = hp[q];      // LDS.128 broadcast
                ffma2(ai, wi[2 * q], hv.x); ffma2(ai, wi[2 * q + 1], hv.y);
                ffma2(af, wf[2 * q], hv.x); ffma2(af, wf[2 * q + 1], hv.y);
                ffma2(ag, wg[2 * q], hv.x); ffma2(ag, wg[2 * q + 1], hv.y);
                ffma2(ao, wo[2 * q], hv.x); ffma2(ao, wo[2 * q + 1], hv.y);
            }
            float iv = fsig(red2(ai));
            float fv = fsig(red2(af));
            float gv = ftanh_(red2(ag));
            float ov = fsig(red2(ao));

            c = fmaf(fv, c, iv * gv);
            float h = ov * ftanh_(c);
            h_sh[l] = h;
            g_ys[t * 32 + l] = h;
            __syncwarp();                   // order STS(h)/STG before reuse/publish

            if (l == 0 && (((t + 1) & (PUB_CHUNK - 1)) == 0)) {
                fence_gpu();                // promote warp's stores to gpu scope
                st_relaxed_gpu(&g_progress, t + 1);
            }
            gx = gxn;
        }
    } else {
        // ---------------- consumer: masked LSTM ----------------
        __shared__ unsigned char tysh[TSTEPS];   // 16 KB
        __shared__ __align__(16) float h_sh[40];
        __shared__ __align__(16) float x_sh[32];
        __shared__ float gsh[160];

        int b = blockIdx.x;
        int myType = (b == 1) ? 1 : (b == 2) ? 0 : 2;
        const float* Wih = (b == 1) ? p_Wih : (b == 2) ? c_Wih : s_Wih;
        const float* Whh = (b == 1) ? p_Whh : (b == 2) ? c_Whh : s_Whh;
        const float* bih = (b == 1) ? p_bih : (b == 2) ? c_bih : s_bih;
        const float* bhh = (b == 1) ? p_bhh : (b == 2) ? c_bhh : s_bhh;

        for (int i = tid; i < TSTEPS; i += 160)
            tysh[i] = (unsigned char)types[i];

        ull wih2[16], whh2[20];
        {
            const ull* p = reinterpret_cast<const ull*>(Wih) + tid * 16;
#pragma unroll
            for (int i = 0; i < 16; i++) wih2[i] = p[i];
            const ull* q = reinterpret_cast<const ull*>(Whh) + tid * 20;
#pragma unroll
            for (int i = 0; i < 20; i++) whh2[i] = q[i];
        }
        float bsum = bih[tid] + bhh[tid];
        float c = 0.0f;
        if (tid < 40) h_sh[tid] = 0.0f;
        __syncthreads();

        int seen = 0;
        for (int t = 0; t < TSTEPS; t++) {
            if (tysh[t] != (unsigned char)myType) continue;   // uniform across block

            if (tid == 0 && seen <= t) {
                while ((seen = ld_acquire_gpu(&g_progress)) <= t) { }
            }
            __syncthreads();

            if (tid < 32) x_sh[tid] = __ldcg(&g_ys[t * 32 + tid]);
            __syncthreads();

            ull a0 = pack2(bsum, 0.0f);
            ull a1 = pack2(0.0f, 0.0f);
            const ulonglong2* xp = reinterpret_cast<const ulonglong2*>(x_sh);
#pragma unroll
            for (int q = 0; q < 8; q++) {
                ulonglong2 v = xp[q];
                ffma2(a0, wih2[2 * q], v.x);
                ffma2(a1, wih2[2 * q + 1], v.y);
            }
            const ulonglong2* hp = reinterpret_cast<const ulonglong2*>(h_sh);
#pragma unroll
            for (int q = 0; q < 10; q++) {
                ulonglong2 v = hp[q];
                ffma2(a0, whh2[2 * q], v.x);
                ffma2(a1, whh2[2 * q + 1], v.y);
            }
            float l0, u0, l1, u1;
            unpack2(a0, l0, u0); unpack2(a1, l1, u1);
            float g = (l0 + l1) + (u0 + u1);
            float v = (tid / 40 == 2) ? ftanh_(g) : fsig(g);   // rows 80..119 = g-gate
            gsh[tid] = v;
            __syncthreads();

            if (tid < 40) {
                float ig = gsh[tid], fg = gsh[40 + tid];
                float gg = gsh[80 + tid], og = gsh[120 + tid];
                c = fg * c + ig * gg;
                h_sh[tid] = og * ftanh_(c);
            }
            __syncthreads();
        }

        if (tid < 40) g_H[myType][tid] = h_sh[tid];
    }
}

// ---------------------------------------------------------------------------
// K3: fusion + MLP -> scalar
// fusion = [next_e(32), user_e(32), H_r(32), H_s(40), H_c(40), H_p(40)]
// ---------------------------------------------------------------------------
__global__ void k_mlp(const int* __restrict__ user,
                      const int* __restrict__ nextitem,
                      const float* __restrict__ item_emb,
                      const float* __restrict__ user_emb,
                      const float* __restrict__ out1_W,
                      const float* __restrict__ out1_b,
                      const float* __restrict__ out2_W,
                      const float* __restrict__ out2_b,
                      float* __restrict__ out)
{
    __shared__ float f[216];
    __shared__ float r16[16];
    int tid = threadIdx.x;   // 64 threads
    int u = user[0], ni = nextitem[0];

    if (tid < 32) {
        f[tid]      = item_emb[tid * NITEMS + ni];
        f[32 + tid] = user_emb[tid * NITEMS + u];
        f[64 + tid] = g_ys[(TSTEPS - 1) * 32 + tid];   // H_r
    }
    if (tid < 40) {
        f[96 + tid]  = g_H[2][tid];   // H_s (type 2)
        f[136 + tid] = g_H[0][tid];   // H_c (type 0)
        f[176 + tid] = g_H[1][tid];   // H_p (type 1)
    }
    __syncthreads();

    if (tid < 16) {
        float acc = out1_b[tid];
        const float* w = out1_W + tid * 216;
        for (int k = 0; k < 216; k++) acc += w[k] * f[k];
        r16[tid] = fmaxf(acc, 0.0f);
    }
    __syncthreads();

    if (tid == 0) {
        float acc = out2_b[0];
        for (int k = 0; k < 16; k++) acc += out2_W[k] * r16[k];
        out[0] = acc;
    }
}

// ---------------------------------------------------------------------------
extern "C" void kernel_launch(void* const* d_in, const int* in_sizes, int n_in,
                              void* d_out, int out_size)
{
    const int*   user      = (const int*)  d_in[0];
    const int*   nextitem  = (const int*)  d_in[1];
    const int*   seq_items = (const int*)  d_in[2];
    const int*   seq_types = (const int*)  d_in[3];
    const float* dwell     = (const float*)d_in[4];
    const float* item_emb  = (const float*)d_in[5];
    const float* user_emb  = (const float*)d_in[6];
    const float* click     = (const float*)d_in[7];
    const float* purchase  = (const float*)d_in[8];
    const float* skipp     = (const float*)d_in[9];
    const float* time_Wih  = (const float*)d_in[10];
    const float* time_Whh  = (const float*)d_in[11];
    const float* time_bih  = (const float*)d_in[12];
    const float* time_bhh  = (const float*)d_in[13];
    const float* p_Wih     = (const float*)d_in[14];
    const float* p_Whh     = (const float*)d_in[15];
    const float* p_bih     = (const float*)d_in[16];
    const float* p_bhh     = (const float*)d_in[17];
    const float* c_Wih     = (const float*)d_in[18];
    const float* c_Whh     = (const float*)d_in[19];
    const float* c_bih     = (const float*)d_in[20];
    const float* c_bhh     = (const float*)d_in[21];
    const float* s_Wih     = (const float*)d_in[22];
    const float* s_Whh     = (const float*)d_in[23];
    const float* s_bih     = (const float*)d_in[24];
    const float* s_bhh     = (const float*)d_in[25];
    const float* out1_W    = (const float*)d_in[26];
    const float* out1_b    = (const float*)d_in[27];
    const float* out2_W    = (const float*)d_in[28];
    const float* out2_b    = (const float*)d_in[29];

    k_precompute_gx<<<TSTEPS, 128>>>(seq_items, seq_types, dwell, item_emb,
                                     click, purchase, skipp,
                                     time_Wih, time_bih, time_bhh);

    k_pipeline<<<4, 160>>>(seq_types, time_Whh,
                           p_Wih, p_Whh, p_bih, p_bhh,
                           c_Wih, c_Whh, c_bih, c_bhh,
                           s_Wih, s_Whh, s_bih, s_bhh);

    k_mlp<<<1, 64>>>(user, nextitem, item_emb, user_emb,
                     out1_W, out1_b, out2_W, out2_b, (float*)d_out);
}

// round 4
// speedup vs baseline: 2.6795x; 1.1830x over previous
#include <cuda_runtime.h>

// ---------------------------------------------------------------------------
// Q_NetWork: time-LSTM (in=10, hid=32) over T=16384 steps, feeding three
// masked LSTMs (in=32, hid=40), fused MLP -> scalar.
//
// R4 changes vs R3 (4.88 ms):
//   * producer = 4 warps (one gate per warp, one warp per SMSP) -> per-warp
//     issue ~4x lower than R3's single warp (which was issue-bound at
//     ~500 cyc/step).
//   * sync via named bar.arrive/bar.sync pairs: each warp blocks on exactly
//     ONE barrier per step; gate values flow one-way (i,f,g warps -> o warp),
//     cell update is lane-local in the o-warp.
// ---------------------------------------------------------------------------

#define TSTEPS 16384
#define NITEMS 1000
#define PUB_CHUNK 32

typedef unsigned long long ull;

// global scratch (device globals: allocation-free per harness rules)
__device__ float g_gx[TSTEPS * 128];   // 8 MB: [t][row(gate*32+elem)] preacts
__device__ float g_ys[TSTEPS * 32];    // 2 MB: time-LSTM hidden states
__device__ float g_H[3][40];           // final hidden per mask type
__device__ int   g_progress;           // producer progress (steps completed)

// ---- fast math helpers ----------------------------------------------------
__device__ __forceinline__ float ftanh_(float x) {
    float y; asm("tanh.approx.f32 %0, %1;" : "=f"(y) : "f"(x)); return y;
}
__device__ __forceinline__ float fsig(float x) {
    return fmaf(0.5f, ftanh_(0.5f * x), 0.5f);
}

// ---- scoped sync primitives ----------------------------------------------
__device__ __forceinline__ void fence_gpu() {
    asm volatile("fence.acq_rel.gpu;" ::: "memory");
}
__device__ __forceinline__ void st_relaxed_gpu(int* p, int v) {
    asm volatile("st.relaxed.gpu.global.b32 [%0], %1;" :: "l"(p), "r"(v) : "memory");
}
__device__ __forceinline__ int ld_acquire_gpu(const int* p) {
    int v; asm volatile("ld.acquire.gpu.global.b32 %0, [%1];" : "=r"(v) : "l"(p) : "memory");
    return v;
}
#define BAR_SYNC(id)   asm volatile("bar.sync %0, 128;"   :: "n"(id) : "memory")
#define BAR_ARRIVE(id) asm volatile("bar.arrive %0, 128;" :: "n"(id) : "memory")

// ---- packed f32x2 FMA (sm_103a FFMA2) -------------------------------------
__device__ __forceinline__ ull pack2(float lo, float hi) {
    ull r; asm("mov.b64 %0, {%1,%2};" : "=l"(r) : "f"(lo), "f"(hi)); return r;
}
__device__ __forceinline__ void unpack2(ull v, float& lo, float& hi) {
    asm("mov.b64 {%0,%1}, %2;" : "=f"(lo), "=f"(hi) : "l"(v));
}
__device__ __forceinline__ void ffma2(ull& acc, ull a, ull b) {
    asm("fma.rn.f32x2 %0, %1, %2, %0;" : "+l"(acc) : "l"(a), "l"(b));
}
__device__ __forceinline__ float red2(ull v) {
    float lo, hi; unpack2(v, lo, hi); return lo + hi;
}

// ---------------------------------------------------------------------------
// K1: per-t gate preactivations for the time LSTM (fully parallel).
// Row r = gate*32 + elem, stored at g_gx[t*128 + r].
// ---------------------------------------------------------------------------
__global__ void k_precompute_gx(const int* __restrict__ items,
                                const int* __restrict__ types,
                                const float* __restrict__ dwell,
                                const float* __restrict__ item_emb,
                                const float* __restrict__ click,
                                const float* __restrict__ purchase,
                                const float* __restrict__ skip,
                                const float* __restrict__ Wih,
                                const float* __restrict__ bih,
                                const float* __restrict__ bhh)
{
    int t = blockIdx.x;
    int tid = threadIdx.x;   // 128 threads

    if (t == 0 && tid == 0) g_progress = 0;  // reset before pipeline kernel

    __shared__ float ie[32];
    __shared__ float xs[10];

    if (tid < 32) ie[tid] = item_emb[tid * NITEMS + items[t]];
    __syncthreads();

    if (tid < 9) {
        int ty = types[t];
        const float* P = (ty == 0) ? click : (ty == 1) ? purchase : skip;
        P += tid * 32;
        float s = 0.0f;
#pragma unroll
        for (int j = 0; j < 32; j++) s += P[j] * ie[j];
        xs[1 + tid] = s;
    } else if (tid == 9) {
        xs[0] = dwell[t];
    }
    __syncthreads();

    float acc = bih[tid] + bhh[tid];
    const float* w = Wih + tid * 10;
#pragma unroll
    for (int i = 0; i < 10; i++) acc += w[i] * xs[i];
    g_gx[t * 128 + tid] = acc;
}

// ---------------------------------------------------------------------------
// K2: persistent pipeline. grid = 4 blocks x 160 threads.
//   block 0: producer (time LSTM), 4 warps: warp w computes gate w
//            (0=i, 1=f, 2=g, 3=o); warp 3 also does the cell update.
//   blocks 1..3: consumers for mask types 1 (p), 0 (c), 2 (s)
// ---------------------------------------------------------------------------
__global__ void __launch_bounds__(160, 1)
k_pipeline(const int* __restrict__ types,
           const float* __restrict__ time_Whh,
           const float* __restrict__ p_Wih, const float* __restrict__ p_Whh,
           const float* __restrict__ p_bih, const float* __restrict__ p_bhh,
           const float* __restrict__ c_Wih, const float* __restrict__ c_Whh,
           const float* __restrict__ c_bih, const float* __restrict__ c_bhh,
           const float* __restrict__ s_Wih, const float* __restrict__ s_Whh,
           const float* __restrict__ s_bih, const float* __restrict__ s_bhh)
{
    int tid = threadIdx.x;

    if (blockIdx.x == 0) {
        // ---------------- producer: time LSTM, 4 warps ----------------
        if (tid >= 128) return;           // 5th warp idle; named bars use 128
        int wid = tid >> 5, l = tid & 31;

        __shared__ __align__(16) float h_sh[32];
        __shared__ float gsh[96];         // i(0..31), f(32..63), g(64..95)

        // warp `wid` lane `l` holds Whh row (wid*32 + l): 16 f32x2 pairs
        ull w2[16];
        {
            const ull* wp = reinterpret_cast<const ull*>(time_Whh + (wid * 32 + l) * 32);
#pragma unroll
            for (int i = 0; i < 16; i++) w2[i] = wp[i];
        }
        float c = 0.0f;
        if (wid == 0) h_sh[l] = 0.0f;
        float gx = g_gx[tid];
        BAR_SYNC(3);

        for (int t = 0; t < TSTEPS; t++) {
            // prefetch next step's preact (one LDG.32, hidden behind step)
            float gxn = (t + 1 < TSTEPS) ? g_gx[(t + 1) * 128 + tid] : 0.0f;

            ull a0 = pack2(gx, 0.0f);
            ull a1 = pack2(0.0f, 0.0f);
            const ulonglong2* hp = reinterpret_cast<const ulonglong2*>(h_sh);
#pragma unroll
            for (int q = 0; q < 8; q++) {
                ulonglong2 hv = hp[q];      // LDS.128 broadcast
                ffma2(a0, w2[2 * q], hv.x);
                ffma2(a1, w2[2 * q + 1], hv.y);
            }
            float g = red2(a0) + red2(a1);
            float v = (wid == 2) ? ftanh_(g) : fsig(g);

            if (wid < 3) {
                gsh[wid * 32 + l] = v;
                BAR_ARRIVE(1);
                BAR_SYNC(2);               // wait for warp 3 to write h
            } else {
                BAR_SYNC(1);               // wait for i,f,g values
                float iv = gsh[l], fv = gsh[32 + l], gv = gsh[64 + l];
                c = fmaf(fv, c, iv * gv);
                float h = v * ftanh_(c);
                h_sh[l] = h;
                g_ys[t * 32 + l] = h;
                if ((t & (PUB_CHUNK - 1)) == (PUB_CHUNK - 1)) {
                    __syncwarp();          // all lanes' STGs before the fence
                    if (l == 0) { fence_gpu(); st_relaxed_gpu(&g_progress, t + 1); }
                }
                BAR_ARRIVE(2);
            }
            gx = gxn;
        }
    } else {
        // ---------------- consumer: masked LSTM ----------------
        __shared__ unsigned char tysh[TSTEPS];   // 16 KB
        __shared__ __align__(16) float h_sh[40];
        __shared__ __align__(16) float x_sh[32];
        __shared__ float gsh[160];

        int b = blockIdx.x;
        int myType = (b == 1) ? 1 : (b == 2) ? 0 : 2;
        const float* Wih = (b == 1) ? p_Wih : (b == 2) ? c_Wih : s_Wih;
        const float* Whh = (b == 1) ? p_Whh : (b == 2) ? c_Whh : s_Whh;
        const float* bih = (b == 1) ? p_bih : (b == 2) ? c_bih : s_bih;
        const float* bhh = (b == 1) ? p_bhh : (b == 2) ? c_bhh : s_bhh;

        for (int i = tid; i < TSTEPS; i += 160)
            tysh[i] = (unsigned char)types[i];

        ull wih2[16], whh2[20];
        {
            const ull* p = reinterpret_cast<const ull*>(Wih) + tid * 16;
#pragma unroll
            for (int i = 0; i < 16; i++) wih2[i] = p[i];
            const ull* q = reinterpret_cast<const ull*>(Whh) + tid * 20;
#pragma unroll
            for (int i = 0; i < 20; i++) whh2[i] = q[i];
        }
        float bsum = bih[tid] + bhh[tid];
        float c = 0.0f;
        if (tid < 40) h_sh[tid] = 0.0f;
        __syncthreads();

        int seen = 0;
        for (int t = 0; t < TSTEPS; t++) {
            if (tysh[t] != (unsigned char)myType) continue;   // uniform across block

            if (tid == 0 && seen <= t) {
                while ((seen = ld_acquire_gpu(&g_progress)) <= t) { }
            }
            __syncthreads();

            if (tid < 32) x_sh[tid] = __ldcg(&g_ys[t * 32 + tid]);
            __syncthreads();

            ull a0 = pack2(bsum, 0.0f);
            ull a1 = pack2(0.0f, 0.0f);
            const ulonglong2* xp = reinterpret_cast<const ulonglong2*>(x_sh);
#pragma unroll
            for (int q = 0; q < 8; q++) {
                ffma2(a0, wih2[2 * q], xp[q].x);
                ffma2(a1, wih2[2 * q + 1], xp[q].y);
            }
            const ulonglong2* hp = reinterpret_cast<const ulonglong2*>(h_sh);
#pragma unroll
            for (int q = 0; q < 10; q++) {
                ffma2(a0, whh2[2 * q], hp[q].x);
                ffma2(a1, whh2[2 * q + 1], hp[q].y);
            }
            float g = red2(a0) + red2(a1);
            float v = (tid / 40 == 2) ? ftanh_(g) : fsig(g);   // rows 80..119 = g-gate
            gsh[tid] = v;
            __syncthreads();

            if (tid < 40) {
                float ig = gsh[tid], fg = gsh[40 + tid];
                float gg = gsh[80 + tid], og = gsh[120 + tid];
                c = fg * c + ig * gg;
                h_sh[tid] = og * ftanh_(c);
            }
            __syncthreads();
        }

        if (tid < 40) g_H[myType][tid] = h_sh[tid];
    }
}

// ---------------------------------------------------------------------------
// K3: fusion + MLP -> scalar
// fusion = [next_e(32), user_e(32), H_r(32), H_s(40), H_c(40), H_p(40)]
// ---------------------------------------------------------------------------
__global__ void k_mlp(const int* __restrict__ user,
                      const int* __restrict__ nextitem,
                      const float* __restrict__ item_emb,
                      const float* __restrict__ user_emb,
                      const float* __restrict__ out1_W,
                      const float* __restrict__ out1_b,
                      const float* __restrict__ out2_W,
                      const float* __restrict__ out2_b,
                      float* __restrict__ out)
{
    __shared__ float f[216];
    __shared__ float r16[16];
    int tid = threadIdx.x;   // 64 threads
    int u = user[0], ni = nextitem[0];

    if (tid < 32) {
        f[tid]      = item_emb[tid * NITEMS + ni];
        f[32 + tid] = user_emb[tid * NITEMS + u];
        f[64 + tid] = g_ys[(TSTEPS - 1) * 32 + tid];   // H_r
    }
    if (tid < 40) {
        f[96 + tid]  = g_H[2][tid];   // H_s (type 2)
        f[136 + tid] = g_H[0][tid];   // H_c (type 0)
        f[176 + tid] = g_H[1][tid];   // H_p (type 1)
    }
    __syncthreads();

    if (tid < 16) {
        float acc = out1_b[tid];
        const float* w = out1_W + tid * 216;
        for (int k = 0; k < 216; k++) acc += w[k] * f[k];
        r16[tid] = fmaxf(acc, 0.0f);
    }
    __syncthreads();

    if (tid == 0) {
        float acc = out2_b[0];
        for (int k = 0; k < 16; k++) acc += out2_W[k] * r16[k];
        out[0] = acc;
    }
}

// ---------------------------------------------------------------------------
extern "C" void kernel_launch(void* const* d_in, const int* in_sizes, int n_in,
                              void* d_out, int out_size)
{
    const int*   user      = (const int*)  d_in[0];
    const int*   nextitem  = (const int*)  d_in[1];
    const int*   seq_items = (const int*)  d_in[2];
    const int*   seq_types = (const int*)  d_in[3];
    const float* dwell     = (const float*)d_in[4];
    const float* item_emb  = (const float*)d_in[5];
    const float* user_emb  = (const float*)d_in[6];
    const float* click     = (const float*)d_in[7];
    const float* purchase  = (const float*)d_in[8];
    const float* skipp     = (const float*)d_in[9];
    const float* time_Wih  = (const float*)d_in[10];
    const float* time_Whh  = (const float*)d_in[11];
    const float* time_bih  = (const float*)d_in[12];
    const float* time_bhh  = (const float*)d_in[13];
    const float* p_Wih     = (const float*)d_in[14];
    const float* p_Whh     = (const float*)d_in[15];
    const float* p_bih     = (const float*)d_in[16];
    const float* p_bhh     = (const float*)d_in[17];
    const float* c_Wih     = (const float*)d_in[18];
    const float* c_Whh     = (const float*)d_in[19];
    const float* c_bih     = (const float*)d_in[20];
    const float* c_bhh     = (const float*)d_in[21];
    const float* s_Wih     = (const float*)d_in[22];
    const float* s_Whh     = (const float*)d_in[23];
    const float* s_bih     = (const float*)d_in[24];
    const float* s_bhh     = (const float*)d_in[25];
    const float* out1_W    = (const float*)d_in[26];
    const float* out1_b    = (const float*)d_in[27];
    const float* out2_W    = (const float*)d_in[28];
    const float* out2_b    = (const float*)d_in[29];

    k_precompute_gx<<<TSTEPS, 128>>>(seq_items, seq_types, dwell, item_emb,
                                     click, purchase, skipp,
                                     time_Wih, time_bih, time_bhh);

    k_pipeline<<<4, 160>>>(seq_types, time_Whh,
                           p_Wih, p_Whh, p_bih, p_bhh,
                           c_Wih, c_Whh, c_bih, c_bhh,
                           s_Wih, s_Whh, s_bih, s_bhh);

    k_mlp<<<1, 64>>>(user, nextitem, item_emb, user_emb,
                     out1_W, out1_b, out2_W, out2_b, (float*)d_out);
}

// round 5
// speedup vs baseline: 3.2179x; 1.2009x over previous
#include <cuda_runtime.h>

// ---------------------------------------------------------------------------
// Q_NetWork: time-LSTM (in=10, hid=32) over T=16384 steps, feeding three
// masked LSTMs (in=32, hid=40), fused MLP -> scalar.
//
// R5 changes vs R4 (4.13 ms):
//   * producer lane mapping transposed: warp w lane l -> gate (l>>3),
//     element 8w+(l&7). All 4 gates of an element are in ONE warp, so the
//     i,f,g,o exchange is 4x SHFL.IDX (no barrier) and the cell update is
//     warp-local. Only h (8 elems/warp) crosses warps.
//   * ONE symmetric named barrier per step (was 2 serial barrier releases),
//     with double-buffered h_sh to avoid the WAR race.
//   * consumer matvec split over 4 accumulators (dep chain 18 -> 10 FFMA2).
// ---------------------------------------------------------------------------

#define TSTEPS 16384
#define NITEMS 1000
#define PUB_CHUNK 32

typedef unsigned long long ull;

// global scratch (device globals: allocation-free per harness rules)
__device__ float g_gx[TSTEPS * 128];   // 8 MB: [t][row(gate*32+elem)] preacts
__device__ float g_ys[TSTEPS * 32];    // 2 MB: time-LSTM hidden states
__device__ float g_H[3][40];           // final hidden per mask type
__device__ int   g_progress;           // producer progress (steps completed)

// ---- fast math helpers ----------------------------------------------------
__device__ __forceinline__ float ftanh_(float x) {
    float y; asm("tanh.approx.f32 %0, %1;" : "=f"(y) : "f"(x)); return y;
}
__device__ __forceinline__ float fsig(float x) {
    return fmaf(0.5f, ftanh_(0.5f * x), 0.5f);
}

// ---- scoped sync primitives ----------------------------------------------
__device__ __forceinline__ void fence_gpu() {
    asm volatile("fence.acq_rel.gpu;" ::: "memory");
}
__device__ __forceinline__ void st_relaxed_gpu(int* p, int v) {
    asm volatile("st.relaxed.gpu.global.b32 [%0], %1;" :: "l"(p), "r"(v) : "memory");
}
__device__ __forceinline__ int ld_acquire_gpu(const int* p) {
    int v; asm volatile("ld.acquire.gpu.global.b32 %0, [%1];" : "=r"(v) : "l"(p) : "memory");
    return v;
}
#define BAR_SYNC(id)   asm volatile("bar.sync %0, 128;"   :: "n"(id) : "memory")

// ---- packed f32x2 FMA (sm_103a FFMA2) -------------------------------------
__device__ __forceinline__ ull pack2(float lo, float hi) {
    ull r; asm("mov.b64 %0, {%1,%2};" : "=l"(r) : "f"(lo), "f"(hi)); return r;
}
__device__ __forceinline__ void unpack2(ull v, float& lo, float& hi) {
    asm("mov.b64 {%0,%1}, %2;" : "=f"(lo), "=f"(hi) : "l"(v));
}
__device__ __forceinline__ void ffma2(ull& acc, ull a, ull b) {
    asm("fma.rn.f32x2 %0, %1, %2, %0;" : "+l"(acc) : "l"(a), "l"(b));
}
__device__ __forceinline__ float red2(ull v) {
    float lo, hi; unpack2(v, lo, hi); return lo + hi;
}

// ---------------------------------------------------------------------------
// K1: per-t gate preactivations for the time LSTM (fully parallel).
// Row r = gate*32 + elem, stored at g_gx[t*128 + r].
// ---------------------------------------------------------------------------
__global__ void k_precompute_gx(const int* __restrict__ items,
                                const int* __restrict__ types,
                                const float* __restrict__ dwell,
                                const float* __restrict__ item_emb,
                                const float* __restrict__ click,
                                const float* __restrict__ purchase,
                                const float* __restrict__ skip,
                                const float* __restrict__ Wih,
                                const float* __restrict__ bih,
                                const float* __restrict__ bhh)
{
    int t = blockIdx.x;
    int tid = threadIdx.x;   // 128 threads

    if (t == 0 && tid == 0) g_progress = 0;  // reset before pipeline kernel

    __shared__ float ie[32];
    __shared__ float xs[10];

    if (tid < 32) ie[tid] = item_emb[tid * NITEMS + items[t]];
    __syncthreads();

    if (tid < 9) {
        int ty = types[t];
        const float* P = (ty == 0) ? click : (ty == 1) ? purchase : skip;
        P += tid * 32;
        float s = 0.0f;
#pragma unroll
        for (int j = 0; j < 32; j++) s += P[j] * ie[j];
        xs[1 + tid] = s;
    } else if (tid == 9) {
        xs[0] = dwell[t];
    }
    __syncthreads();

    float acc = bih[tid] + bhh[tid];
    const float* w = Wih + tid * 10;
#pragma unroll
    for (int i = 0; i < 10; i++) acc += w[i] * xs[i];
    g_gx[t * 128 + tid] = acc;
}

// ---------------------------------------------------------------------------
// K2: persistent pipeline. grid = 4 blocks x 160 threads.
//   block 0: producer (time LSTM), 4 warps; warp w lane l owns
//            gate (l>>3) of element 8w+(l&7).
//   blocks 1..3: consumers for mask types 1 (p), 0 (c), 2 (s)
// ---------------------------------------------------------------------------
__global__ void __launch_bounds__(160, 1)
k_pipeline(const int* __restrict__ types,
           const float* __restrict__ time_Whh,
           const float* __restrict__ p_Wih, const float* __restrict__ p_Whh,
           const float* __restrict__ p_bih, const float* __restrict__ p_bhh,
           const float* __restrict__ c_Wih, const float* __restrict__ c_Whh,
           const float* __restrict__ c_bih, const float* __restrict__ c_bhh,
           const float* __restrict__ s_Wih, const float* __restrict__ s_Whh,
           const float* __restrict__ s_bih, const float* __restrict__ s_bhh)
{
    int tid = threadIdx.x;

    if (blockIdx.x == 0) {
        // ---------------- producer: time LSTM, 4 warps, 1 bar/step --------
        if (tid >= 128) return;           // 5th warp idle; named bar uses 128
        int wid = tid >> 5, l = tid & 31;
        int gate = l >> 3, eloc = l & 7;
        int e = wid * 8 + eloc;           // element 0..31
        int row = gate * 32 + e;          // Whh / gx row

        __shared__ __align__(16) float h_buf[2][32];

        ull w2[16];
        {
            const ull* wp = reinterpret_cast<const ull*>(time_Whh + row * 32);
#pragma unroll
            for (int i = 0; i < 16; i++) w2[i] = wp[i];
        }
        float c = 0.0f;
        if (l < 8) h_buf[0][e] = 0.0f;    // lanes 0..7 of each warp init 8 elems
        float gx = g_gx[row];             // t = 0
        BAR_SYNC(1);

        bool isg = (gate == 2);
        for (int t = 0; t < TSTEPS; t++) {
            // chunked progress publish (off critical path, ~3 cyc/step amort.)
            if (tid == 0 && t && ((t & (PUB_CHUNK - 1)) == 0)) {
                fence_gpu(); st_relaxed_gpu(&g_progress, t);
            }
            // prefetch next step's preact (LDG hidden behind the step)
            float gxn = (t + 1 < TSTEPS) ? g_gx[(t + 1) * 128 + row] : 0.0f;

            ull a0 = pack2(gx, 0.0f);
            ull a1 = pack2(0.0f, 0.0f);
            const ulonglong2* hp = reinterpret_cast<const ulonglong2*>(h_buf[t & 1]);
#pragma unroll
            for (int q = 0; q < 8; q++) {
                ulonglong2 hv = hp[q];      // LDS.128 broadcast
                ffma2(a0, w2[2 * q], hv.x);
                ffma2(a1, w2[2 * q + 1], hv.y);
            }
            float gsum = red2(a0) + red2(a1);
            // branchless gate activation: one MUFU per lane
            float arg = isg ? gsum : 0.5f * gsum;
            float tv = ftanh_(arg);
            float v = isg ? tv : fmaf(0.5f, tv, 0.5f);

            // intra-warp gate exchange (all gates of elem e live in this warp)
            float iv = __shfl_sync(0xffffffffu, v, eloc);
            float fv = __shfl_sync(0xffffffffu, v, 8 + eloc);
            float gg = __shfl_sync(0xffffffffu, v, 16 + eloc);
            float ov = __shfl_sync(0xffffffffu, v, 24 + eloc);

            c = fmaf(fv, c, iv * gg);          // replicated across gate-lanes
            float h = ov * ftanh_(c);

            if (l < 8) {
                h_buf[(t + 1) & 1][e] = h;
                g_ys[t * 32 + e] = h;
            }
            BAR_SYNC(1);                       // single barrier per step
            gx = gxn;
        }
        if (tid == 0) { fence_gpu(); st_relaxed_gpu(&g_progress, TSTEPS); }
    } else {
        // ---------------- consumer: masked LSTM ----------------
        __shared__ unsigned char tysh[TSTEPS];   // 16 KB
        __shared__ __align__(16) float h_sh[40];
        __shared__ __align__(16) float x_sh[32];
        __shared__ float gsh[160];

        int b = blockIdx.x;
        int myType = (b == 1) ? 1 : (b == 2) ? 0 : 2;
        const float* Wih = (b == 1) ? p_Wih : (b == 2) ? c_Wih : s_Wih;
        const float* Whh = (b == 1) ? p_Whh : (b == 2) ? c_Whh : s_Whh;
        const float* bih = (b == 1) ? p_bih : (b == 2) ? c_bih : s_bih;
        const float* bhh = (b == 1) ? p_bhh : (b == 2) ? c_bhh : s_bhh;

        for (int i = tid; i < TSTEPS; i += 160)
            tysh[i] = (unsigned char)types[i];

        ull wih2[16], whh2[20];
        {
            const ull* p = reinterpret_cast<const ull*>(Wih) + tid * 16;
#pragma unroll
            for (int i = 0; i < 16; i++) wih2[i] = p[i];
            const ull* q = reinterpret_cast<const ull*>(Whh) + tid * 20;
#pragma unroll
            for (int i = 0; i < 20; i++) whh2[i] = q[i];
        }
        float bsum = bih[tid] + bhh[tid];
        float c = 0.0f;
        if (tid < 40) h_sh[tid] = 0.0f;
        __syncthreads();

        int seen = 0;
        for (int t = 0; t < TSTEPS; t++) {
            if (tysh[t] != (unsigned char)myType) continue;   // uniform across block

            if (tid == 0 && seen <= t) {
                while ((seen = ld_acquire_gpu(&g_progress)) <= t) { }
            }
            __syncthreads();

            if (tid < 32) x_sh[tid] = __ldcg(&g_ys[t * 32 + tid]);
            __syncthreads();

            // 4 accumulators: dep chains of 8/8/10/10 instead of 18/18
            ull a0 = pack2(bsum, 0.0f);
            ull a1 = pack2(0.0f, 0.0f);
            ull a2 = pack2(0.0f, 0.0f);
            ull a3 = pack2(0.0f, 0.0f);
            const ulonglong2* xp = reinterpret_cast<const ulonglong2*>(x_sh);
#pragma unroll
            for (int q = 0; q < 8; q++) {
                ffma2(a0, wih2[2 * q], xp[q].x);
                ffma2(a1, wih2[2 * q + 1], xp[q].y);
            }
            const ulonglong2* hp = reinterpret_cast<const ulonglong2*>(h_sh);
#pragma unroll
            for (int q = 0; q < 10; q++) {
                ffma2(a2, whh2[2 * q], hp[q].x);
                ffma2(a3, whh2[2 * q + 1], hp[q].y);
            }
            float g = (red2(a0) + red2(a1)) + (red2(a2) + red2(a3));
            float v = (tid / 40 == 2) ? ftanh_(g) : fsig(g);   // rows 80..119 = g-gate
            gsh[tid] = v;
            __syncthreads();

            if (tid < 40) {
                float ig = gsh[tid], fg = gsh[40 + tid];
                float gg = gsh[80 + tid], og = gsh[120 + tid];
                c = fg * c + ig * gg;
                h_sh[tid] = og * ftanh_(c);
            }
            __syncthreads();
        }

        if (tid < 40) g_H[myType][tid] = h_sh[tid];
    }
}

// ---------------------------------------------------------------------------
// K3: fusion + MLP -> scalar
// fusion = [next_e(32), user_e(32), H_r(32), H_s(40), H_c(40), H_p(40)]
// ---------------------------------------------------------------------------
__global__ void k_mlp(const int* __restrict__ user,
                      const int* __restrict__ nextitem,
                      const float* __restrict__ item_emb,
                      const float* __restrict__ user_emb,
                      const float* __restrict__ out1_W,
                      const float* __restrict__ out1_b,
                      const float* __restrict__ out2_W,
                      const float* __restrict__ out2_b,
                      float* __restrict__ out)
{
    __shared__ float f[216];
    __shared__ float r16[16];
    int tid = threadIdx.x;   // 64 threads
    int u = user[0], ni = nextitem[0];

    if (tid < 32) {
        f[tid]      = item_emb[tid * NITEMS + ni];
        f[32 + tid] = user_emb[tid * NITEMS + u];
        f[64 + tid] = g_ys[(TSTEPS - 1) * 32 + tid];   // H_r
    }
    if (tid < 40) {
        f[96 + tid]  = g_H[2][tid];   // H_s (type 2)
        f[136 + tid] = g_H[0][tid];   // H_c (type 0)
        f[176 + tid] = g_H[1][tid];   // H_p (type 1)
    }
    __syncthreads();

    if (tid < 16) {
        float acc = out1_b[tid];
        const float* w = out1_W + tid * 216;
        for (int k = 0; k < 216; k++) acc += w[k] * f[k];
        r16[tid] = fmaxf(acc, 0.0f);
    }
    __syncthreads();

    if (tid == 0) {
        float acc = out2_b[0];
        for (int k = 0; k < 16; k++) acc += out2_W[k] * r16[k];
        out[0] = acc;
    }
}

// ---------------------------------------------------------------------------
extern "C" void kernel_launch(void* const* d_in, const int* in_sizes, int n_in,
                              void* d_out, int out_size)
{
    const int*   user      = (const int*)  d_in[0];
    const int*   nextitem  = (const int*)  d_in[1];
    const int*   seq_items = (const int*)  d_in[2];
    const int*   seq_types = (const int*)  d_in[3];
    const float* dwell     = (const float*)d_in[4];
    const float* item_emb  = (const float*)d_in[5];
    const float* user_emb  = (const float*)d_in[6];
    const float* click     = (const float*)d_in[7];
    const float* purchase  = (const float*)d_in[8];
    const float* skipp     = (const float*)d_in[9];
    const float* time_Wih  = (const float*)d_in[10];
    const float* time_Whh  = (const float*)d_in[11];
    const float* time_bih  = (const float*)d_in[12];
    const float* time_bhh  = (const float*)d_in[13];
    const float* p_Wih     = (const float*)d_in[14];
    const float* p_Whh     = (const float*)d_in[15];
    const float* p_bih     = (const float*)d_in[16];
    const float* p_bhh     = (const float*)d_in[17];
    const float* c_Wih     = (const float*)d_in[18];
    const float* c_Whh     = (const float*)d_in[19];
    const float* c_bih     = (const float*)d_in[20];
    const float* c_bhh     = (const float*)d_in[21];
    const float* s_Wih     = (const float*)d_in[22];
    const float* s_Whh     = (const float*)d_in[23];
    const float* s_bih     = (const float*)d_in[24];
    const float* s_bhh     = (const float*)d_in[25];
    const float* out1_W    = (const float*)d_in[26];
    const float* out1_b    = (const float*)d_in[27];
    const float* out2_W    = (const float*)d_in[28];
    const float* out2_b    = (const float*)d_in[29];

    k_precompute_gx<<<TSTEPS, 128>>>(seq_items, seq_types, dwell, item_emb,
                                     click, purchase, skipp,
                                     time_Wih, time_bih, time_bhh);

    k_pipeline<<<4, 160>>>(seq_types, time_Whh,
                           p_Wih, p_Whh, p_bih, p_bhh,
                           c_Wih, c_Whh, c_bih, c_bhh,
                           s_Wih, s_Whh, s_bih, s_bhh);

    k_mlp<<<1, 64>>>(user, nextitem, item_emb, user_emb,
                     out1_W, out1_b, out2_W, out2_b, (float*)d_out);
}